// round 13
// baseline (speedup 1.0000x reference)
#include <cuda_runtime.h>
#include <cstdint>

#define SEQ 4096
#define HID 256
#define EMB 256
#define NEG_LOG2E -1.44269504088896340736f

// ---------------------------------------------------------------------------
// Scratch: x_proj[t][j] pre-scaled by -log2e (4096 x 256 fp32 = 4 MB).
// ---------------------------------------------------------------------------
__device__ float g_xproj[SEQ * HID];

// ---------------------------------------------------------------------------
// Phase 1: x_proj = (embedding[tokens] @ wx_w.T + wx_b) * (-log2e)
// ---------------------------------------------------------------------------
#define TOK_PER_BLK 16

__global__ __launch_bounds__(256) void xproj_kernel(
    const int* __restrict__ tokens,
    const float* __restrict__ embedding,
    const float* __restrict__ wx_w,
    const float* __restrict__ wx_b)
{
    __shared__ float emb_sm[TOK_PER_BLK * EMB];
    const int tid = threadIdx.x;
    const int t0  = blockIdx.x * TOK_PER_BLK;

    #pragma unroll
    for (int i = 0; i < TOK_PER_BLK; i++) {
        long tok = (long)tokens[t0 + i];
        emb_sm[i * EMB + tid] = embedding[tok * (long)EMB + tid];
    }
    __syncthreads();

    float acc[TOK_PER_BLK];
    #pragma unroll
    for (int i = 0; i < TOK_PER_BLK; i++) acc[i] = 0.f;

    const float4* wrow = reinterpret_cast<const float4*>(wx_w + tid * EMB);
    #pragma unroll 4
    for (int k4 = 0; k4 < EMB / 4; k4++) {
        float4 w = wrow[k4];
        #pragma unroll
        for (int i = 0; i < TOK_PER_BLK; i++) {
            float4 e = *reinterpret_cast<const float4*>(&emb_sm[i * EMB + 4 * k4]);
            acc[i] += w.x * e.x + w.y * e.y + w.z * e.z + w.w * e.w;
        }
    }

    const float b = wx_b[tid];
    #pragma unroll
    for (int i = 0; i < TOK_PER_BLK; i++)
        g_xproj[(t0 + i) * HID + tid] = (acc[i] + b) * NEG_LOG2E;
}

// ---------------------------------------------------------------------------
// Phase 2: serial recurrence, 8-CTA cluster, BARRIER-FREE with owner fastpath.
//
// CTA r owns h slice [r*32, r*32+32); dots read only that slice, so h never
// crosses the cluster — only 1-float partials do.
//
// Epoch-tagged h (R11 protocol, proven): owner warp stores
// hbuf[nxt][lane] = h + k', k' = ((t+1)&3)+1. SENDER warps lane-poll one
// hbuf word for uint range [float(k), float(k+1)] (stale epochs differ by 2
// mod 4 -> disjoint), __syncwarp, vector-load, dot, cancel tag with one FMA
// (s = dot - k*rowsum). The OWNER warp never waits: it wrote h itself, so a
// single __syncwarp after the publish makes all 32 lanes' stores visible for
// its own next-step read. The critical-path agent pays 23 cyc instead of a
// bar or a poll.
//
// All z-contributors pre-scaled by -log2e: sigmoid = rcp(1 + ex2(acc)).
//
// Ordering (identical causal chains to R11, which passed):
//  - inbox re-arm (volatile STS) precedes the tagged publish (plain store
//    kept behind it by the asm memory clobbers); any CTA's next write into
//    that row (t+2) chains through consuming our t+1 partials -> after our
//    publish -> after the re-arm.
//  - hbuf[cur] overwrite at t+2 chains through every local warp's t-read
//    via the inter-CTA partial round trip.
// ---------------------------------------------------------------------------
#define NCTA 8
#define THREADS2 256
#define SLICE 32          // outputs (and k's) per CTA
#define SENTB 0xFFFFFFFFu
#define INBOX_WORDS 256   // 32 outputs x 8 sender slots (one buffer)

__device__ __forceinline__ uint32_t smem_u32(const void* p) {
    uint32_t a;
    asm("{ .reg .u64 t; cvta.to.shared.u64 t, %1; cvt.u32.u64 %0, t; }"
        : "=r"(a) : "l"(p));
    return a;
}
__device__ __forceinline__ uint32_t mapa_rank(uint32_t a, uint32_t rank) {
    uint32_t r;
    asm("mapa.shared::cluster.u32 %0, %1, %2;" : "=r"(r) : "r"(a), "r"(rank));
    return r;
}
__device__ __forceinline__ void st_remote_f32(uint32_t a, float v) {
    asm volatile("st.shared::cluster.f32 [%0], %1;" :: "r"(a), "f"(v) : "memory");
}
__device__ __forceinline__ void fma2(unsigned long long& acc,
                                     unsigned long long a, unsigned long long b) {
    asm("fma.rn.f32x2 %0, %1, %2, %0;" : "+l"(acc) : "l"(a), "l"(b));
}
__device__ __forceinline__ void add2(unsigned long long& d,
                                     unsigned long long a, unsigned long long b) {
    asm("add.rn.f32x2 %0, %1, %2;" : "=l"(d) : "l"(a), "l"(b));
}
__device__ __forceinline__ unsigned long long pack2(float x, float y) {
    unsigned long long v;
    asm("mov.b64 %0, {%1, %2};" : "=l"(v) : "f"(x), "f"(y));
    return v;
}
__device__ __forceinline__ void unpack2(unsigned long long v, float& x, float& y) {
    asm("mov.b64 {%0, %1}, %2;" : "=f"(x), "=f"(y) : "l"(v));
}
__device__ __forceinline__ void ldsv4(uint32_t addr, unsigned& a, unsigned& b,
                                      unsigned& c, unsigned& d) {
    asm volatile("ld.volatile.shared.v4.u32 {%0,%1,%2,%3}, [%4];"
                 : "=r"(a), "=r"(b), "=r"(c), "=r"(d) : "r"(addr));
}
__device__ __forceinline__ void stsv4(uint32_t addr, unsigned a, unsigned b,
                                      unsigned c, unsigned d) {
    asm volatile("st.volatile.shared.v4.u32 [%0], {%1,%2,%3,%4};"
                 :: "r"(addr), "r"(a), "r"(b), "r"(c), "r"(d) : "memory");
}
__device__ __forceinline__ void stsv1(uint32_t addr, unsigned v) {
    asm volatile("st.volatile.shared.u32 [%0], %1;"
                 :: "r"(addr), "r"(v) : "memory");
}
// sigmoid tail on pre-scaled acc = -z*log2e : h = 1/(1 + 2^acc)
__device__ __forceinline__ float sigmoid_scaled(float acc) {
    float e, h;
    asm("ex2.approx.f32 %0, %1;" : "=f"(e) : "f"(acc));
    asm("rcp.approx.f32 %0, %1;" : "=f"(h) : "f"(e + 1.0f));
    return h;
}

__global__ __launch_bounds__(THREADS2, 1) __cluster_dims__(NCTA, 1, 1)
void rnn_kernel(const float* __restrict__ wh_w,
                const float* __restrict__ wh_b,
                float* __restrict__ out)
{
    __shared__ __align__(16) float    hbuf[2][SLICE];        // tagged own slice
    __shared__ __align__(16) unsigned inbox[2][INBOX_WORDS]; // [o&31][sender]

    const int tid = threadIdx.x;
    uint32_t rank; asm("mov.u32 %0, %%cluster_ctarank;" : "=r"(rank));

    const int o    = tid;            // GLOBAL output index 0..255
    const int lane = tid & 31;
    const int own  = o >> 5;         // owner CTA (= warp id) of output o
    const bool owner = (own == (int)rank);

    // Register-resident packed weights (pre-scaled) + rowsum (tag cancel)
    unsigned long long w[SLICE / 2];
    float rowsum = 0.f;
    {
        const float* row = wh_w + o * HID + (int)rank * SLICE;
        #pragma unroll
        for (int i = 0; i < SLICE / 2; i++) {
            float w0 = row[2 * i] * NEG_LOG2E;
            float w1 = row[2 * i + 1] * NEG_LOG2E;
            w[i] = pack2(w0, w1);
            rowsum += w0 + w1;
        }
    }

    // Init: hbuf[0] = h0 + tag1 = 1.0 (h0 = 0); hbuf[1] = 0 (matches no tag).
    // Both inbox buffers armed with sentinel.
    if (tid < SLICE) { hbuf[0][tid] = 1.0f; hbuf[1][tid] = 0.0f; }
    reinterpret_cast<unsigned*>(inbox)[tid]            = SENTB;
    reinterpret_cast<unsigned*>(inbox)[tid + THREADS2] = SENTB;

    float bias = 0.f, bxp = 0.f, hn = 0.f;
    if (owner) {
        bias = wh_b[o] * NEG_LOG2E;
        bxp  = bias + g_xproj[o];          // g_xproj already scaled
    }
    __syncthreads();
    // One-time: all CTAs' init visible before any remote store.
    asm volatile("barrier.cluster.arrive.aligned;" ::: "memory");
    asm volatile("barrier.cluster.wait.aligned;"   ::: "memory");

    // Sender: remote address of owner CTA's inbox slot [buf0][(o&31)*8 + rank]
    uint32_t dst = 0;
    if (!owner)
        dst = mapa_rank(smem_u32(&inbox[0][0]), (uint32_t)own)
            + (uint32_t)(((o & 31) << 3) + (int)rank) * 4u;
    // Owner: local base of its inbox row (32B, 16B-aligned)
    const uint32_t rowbase = smem_u32(&inbox[0][(o & 31) << 3]);
    const uint32_t BUFB = INBOX_WORDS * 4u;   // bytes between inbox buffers

    for (int t = 0; t < SEQ; t++) {
        const int   cur = t & 1;
        const int   nxt = cur ^ 1;
        const float kf  = (float)((t & 3) + 1);        // tag consumed this step
        const float kfn = (float)(((t + 1) & 3) + 1);  // tag we will store

        float bxp_next = 0.f;
        if (owner && (t + 1 < SEQ))
            bxp_next = bias + __ldg(&g_xproj[(t + 1) * HID + o]);

        // ---- h pickup ----
        if (!owner) {
            // sender: lane-poll this epoch's tag on ONE hbuf word, then sync
            const unsigned lo = __float_as_uint(kf);
            const unsigned hi = __float_as_uint(kf + 1.0f);
            volatile unsigned* ph =
                reinterpret_cast<volatile unsigned*>(&hbuf[cur][lane]);
            unsigned u = *ph;
            while (u < lo || u > hi) u = *ph;
            __syncwarp();
        }
        // owner: wrote hbuf[cur] itself last iter + __syncwarp'd -> no wait.

        // ---- 32-MAC partial over tagged slice: 4 chains + add2 tree ----
        const ulonglong2* h2 =
            reinterpret_cast<const ulonglong2*>(&hbuf[cur][0]);
        ulonglong2 hv0 = h2[0], hv1 = h2[1], hv2 = h2[2], hv3 = h2[3];
        ulonglong2 hv4 = h2[4], hv5 = h2[5], hv6 = h2[6], hv7 = h2[7];
        unsigned long long a0 = 0ull, a1 = 0ull, a2 = 0ull, a3 = 0ull;
        fma2(a0, w[0],  hv0.x); fma2(a1, w[1],  hv0.y);
        fma2(a2, w[2],  hv1.x); fma2(a3, w[3],  hv1.y);
        fma2(a0, w[4],  hv2.x); fma2(a1, w[5],  hv2.y);
        fma2(a2, w[6],  hv3.x); fma2(a3, w[7],  hv3.y);
        fma2(a0, w[8],  hv4.x); fma2(a1, w[9],  hv4.y);
        fma2(a2, w[10], hv5.x); fma2(a3, w[11], hv5.y);
        fma2(a0, w[12], hv6.x); fma2(a1, w[13], hv6.y);
        fma2(a2, w[14], hv7.x); fma2(a3, w[15], hv7.y);
        unsigned long long b0, b1, sp;
        add2(b0, a0, a1); add2(b1, a2, a3); add2(sp, b0, b1);
        float x0, y0;
        unpack2(sp, x0, y0);
        float s = fmaf(-kf, rowsum, x0 + y0);   // cancel tag*rowsum

        if (!owner) {
            // ship partial straight to the owner CTA
            st_remote_f32(dst + (uint32_t)cur * BUFB, s);
        } else {
            // deposit own partial (bias'+xp' folded) during the flight
            const uint32_t rb = rowbase + (uint32_t)cur * BUFB;
            stsv1(rb + (uint32_t)rank * 4u, __float_as_uint(s + bxp));
            // poll the full 8-slot row (2x16B volatile loads)
            unsigned v0, v1, v2, v3, v4, v5, v6, v7;
            for (;;) {
                ldsv4(rb,      v0, v1, v2, v3);
                ldsv4(rb + 16, v4, v5, v6, v7);
                if (v0 != SENTB && v1 != SENTB && v2 != SENTB && v3 != SENTB &&
                    v4 != SENTB && v5 != SENTB && v6 != SENTB && v7 != SENTB)
                    break;
            }
            // re-arm for t+2 (volatile; ordered before the tagged publish)
            stsv4(rb,      SENTB, SENTB, SENTB, SENTB);
            stsv4(rb + 16, SENTB, SENTB, SENTB, SENTB);

            float z = ((__uint_as_float(v0) + __uint_as_float(v1)) +
                       (__uint_as_float(v2) + __uint_as_float(v3))) +
                      ((__uint_as_float(v4) + __uint_as_float(v5)) +
                       (__uint_as_float(v6) + __uint_as_float(v7)));
            hn = sigmoid_scaled(z);            // z is -z_true*log2e
            hbuf[nxt][lane] = hn + kfn;        // tagged publish (no bar)
            __syncwarp();                      // own-warp visibility for t+1
            bxp = bxp_next;
        }
    }

    if (owner) out[o] = hn;
}

// ---------------------------------------------------------------------------
// kernel_launch
//   d_in: [0] tokens i32[4096], [1] embedding f32[128000*256],
//         [2] wx_w f32[256*256], [3] wx_b f32[256],
//         [4] wh_w f32[256*256], [5] wh_b f32[256]
// ---------------------------------------------------------------------------
extern "C" void kernel_launch(void* const* d_in, const int* in_sizes, int n_in,
                              void* d_out, int out_size)
{
    const int*   tokens    = (const int*)d_in[0];
    const float* embedding = (const float*)d_in[1];
    const float* wx_w      = (const float*)d_in[2];
    const float* wx_b      = (const float*)d_in[3];
    const float* wh_w      = (const float*)d_in[4];
    const float* wh_b      = (const float*)d_in[5];
    float*       out       = (float*)d_out;

    xproj_kernel<<<SEQ / TOK_PER_BLK, 256>>>(tokens, embedding, wx_w, wx_b);
    rnn_kernel<<<NCTA, THREADS2>>>(wh_w, wh_b, out);
}

// round 15
// speedup vs baseline: 1.0623x; 1.0623x over previous
#include <cuda_runtime.h>
#include <cstdint>

#define SEQ 4096
#define HID 256
#define EMB 256
#define NEG_LOG2E -1.44269504088896340736f

// ---------------------------------------------------------------------------
// Scratch: x_proj[t][j] pre-scaled by -log2e (4096 x 256 fp32 = 4 MB).
// ---------------------------------------------------------------------------
__device__ float g_xproj[SEQ * HID];

// ---------------------------------------------------------------------------
// Phase 1: x_proj = (embedding[tokens] @ wx_w.T + wx_b) * (-log2e)
// ---------------------------------------------------------------------------
#define TOK_PER_BLK 16

__global__ __launch_bounds__(256) void xproj_kernel(
    const int* __restrict__ tokens,
    const float* __restrict__ embedding,
    const float* __restrict__ wx_w,
    const float* __restrict__ wx_b)
{
    __shared__ float emb_sm[TOK_PER_BLK * EMB];
    const int tid = threadIdx.x;
    const int t0  = blockIdx.x * TOK_PER_BLK;

    #pragma unroll
    for (int i = 0; i < TOK_PER_BLK; i++) {
        long tok = (long)tokens[t0 + i];
        emb_sm[i * EMB + tid] = embedding[tok * (long)EMB + tid];
    }
    __syncthreads();

    float acc[TOK_PER_BLK];
    #pragma unroll
    for (int i = 0; i < TOK_PER_BLK; i++) acc[i] = 0.f;

    const float4* wrow = reinterpret_cast<const float4*>(wx_w + tid * EMB);
    #pragma unroll 4
    for (int k4 = 0; k4 < EMB / 4; k4++) {
        float4 w = wrow[k4];
        #pragma unroll
        for (int i = 0; i < TOK_PER_BLK; i++) {
            float4 e = *reinterpret_cast<const float4*>(&emb_sm[i * EMB + 4 * k4]);
            acc[i] += w.x * e.x + w.y * e.y + w.z * e.z + w.w * e.w;
        }
    }

    const float b = wx_b[tid];
    #pragma unroll
    for (int i = 0; i < TOK_PER_BLK; i++)
        g_xproj[(t0 + i) * HID + tid] = (acc[i] + b) * NEG_LOG2E;
}

// ---------------------------------------------------------------------------
// Phase 2: serial recurrence, 8-CTA cluster — R10 skeleton (proven fastest),
// loop unrolled x2, 4-chain dot, -log2e prescale.
//
// CTA r owns h slice [r*32, r*32+32); every dot reads ONLY that slice, so h
// never crosses the cluster — only 1-float partials do. One thread per
// GLOBAL output (o = tid):
//   sender warp (7 of 8): 16 fma2 over the slice -> one st.shared::cluster
//     into owner CTA's inbox[buf][(o&31)*8 + rank].
//   owner warp (warp 'rank'): dot -> deposit (s + bias' + xp' folded) ->
//     poll full 8-slot row (2x16B volatile loads) -> re-arm -> sum8 ->
//     sigmoid (ex2+rcp on prescaled acc) -> store h -> bar.
// One __syncthreads per step: publishes hbuf[nxt], drains owner's re-arm,
// closes reads of hbuf[cur].
//
// Sentinel protocol (distance-2, proven R8/R10/R11/R12): inbox idles at
// 0xFFFFFFFF (NaN pattern finite dots never produce). Owner re-arms consumed
// words before its end-of-step bar (BAR.SYNC drains STS); senders' t+1 ships
// are after that bar; every other owner consumes them before its t+1 bar;
// their senders' t+2 writes into the re-armed row are causally after that.
// ---------------------------------------------------------------------------
#define NCTA 8
#define THREADS2 256
#define SLICE 32          // outputs (and k's) per CTA
#define SENTB 0xFFFFFFFFu
#define INBOX_WORDS 256   // 32 outputs x 8 sender slots (one buffer)

__device__ __forceinline__ uint32_t smem_u32(const void* p) {
    uint32_t a;
    asm("{ .reg .u64 t; cvta.to.shared.u64 t, %1; cvt.u32.u64 %0, t; }"
        : "=r"(a) : "l"(p));
    return a;
}
__device__ __forceinline__ uint32_t mapa_rank(uint32_t a, uint32_t rank) {
    uint32_t r;
    asm("mapa.shared::cluster.u32 %0, %1, %2;" : "=r"(r) : "r"(a), "r"(rank));
    return r;
}
__device__ __forceinline__ void st_remote_f32(uint32_t a, float v) {
    asm volatile("st.shared::cluster.f32 [%0], %1;" :: "r"(a), "f"(v) : "memory");
}
__device__ __forceinline__ void fma2(unsigned long long& acc,
                                     unsigned long long a, unsigned long long b) {
    asm("fma.rn.f32x2 %0, %1, %2, %0;" : "+l"(acc) : "l"(a), "l"(b));
}
__device__ __forceinline__ void add2(unsigned long long& d,
                                     unsigned long long a, unsigned long long b) {
    asm("add.rn.f32x2 %0, %1, %2;" : "=l"(d) : "l"(a), "l"(b));
}
__device__ __forceinline__ unsigned long long pack2(float x, float y) {
    unsigned long long v;
    asm("mov.b64 %0, {%1, %2};" : "=l"(v) : "f"(x), "f"(y));
    return v;
}
__device__ __forceinline__ void unpack2(unsigned long long v, float& x, float& y) {
    asm("mov.b64 {%0, %1}, %2;" : "=f"(x), "=f"(y) : "l"(v));
}
__device__ __forceinline__ void ldsv4(uint32_t addr, unsigned& a, unsigned& b,
                                      unsigned& c, unsigned& d) {
    asm volatile("ld.volatile.shared.v4.u32 {%0,%1,%2,%3}, [%4];"
                 : "=r"(a), "=r"(b), "=r"(c), "=r"(d) : "r"(addr));
}
__device__ __forceinline__ void stsv4(uint32_t addr, unsigned a, unsigned b,
                                      unsigned c, unsigned d) {
    asm volatile("st.volatile.shared.v4.u32 [%0], {%1,%2,%3,%4};"
                 :: "r"(addr), "r"(a), "r"(b), "r"(c), "r"(d) : "memory");
}
__device__ __forceinline__ void stsv1(uint32_t addr, unsigned v) {
    asm volatile("st.volatile.shared.u32 [%0], %1;"
                 :: "r"(addr), "r"(v) : "memory");
}
// sigmoid tail on pre-scaled acc = -z*log2e : h = 1/(1 + 2^acc)
__device__ __forceinline__ float sigmoid_scaled(float acc) {
    float e, h;
    asm("ex2.approx.f32 %0, %1;" : "=f"(e) : "f"(acc));
    asm("rcp.approx.f32 %0, %1;" : "=f"(h) : "f"(e + 1.0f));
    return h;
}

__global__ __launch_bounds__(THREADS2, 1) __cluster_dims__(NCTA, 1, 1)
void rnn_kernel(const float* __restrict__ wh_w,
                const float* __restrict__ wh_b,
                float* __restrict__ out)
{
    __shared__ __align__(16) float    hbuf[2][SLICE];        // own h slice only
    __shared__ __align__(16) unsigned inbox[2][INBOX_WORDS]; // [o&31][sender]

    const int tid = threadIdx.x;
    uint32_t rank; asm("mov.u32 %0, %%cluster_ctarank;" : "=r"(rank));

    const int o    = tid;            // GLOBAL output index 0..255
    const int own  = o >> 5;         // owner CTA (= warp id) of output o
    const bool owner = (own == (int)rank);

    // Register-resident packed weights, pre-scaled by -log2e
    unsigned long long w[SLICE / 2];
    {
        const float* row = wh_w + o * HID + (int)rank * SLICE;
        #pragma unroll
        for (int i = 0; i < SLICE / 2; i++)
            w[i] = pack2(row[2 * i] * NEG_LOG2E, row[2 * i + 1] * NEG_LOG2E);
    }

    // Init: h0 = 0 (own slice); both inbox buffers armed with sentinel.
    if (tid < SLICE) { hbuf[0][tid] = 0.f; }
    reinterpret_cast<unsigned*>(inbox)[tid]            = SENTB;
    reinterpret_cast<unsigned*>(inbox)[tid + THREADS2] = SENTB;

    float bias = 0.f, bxp = 0.f, hn = 0.f;
    if (owner) {
        bias = wh_b[o] * NEG_LOG2E;
        bxp  = bias + g_xproj[o];          // g_xproj already scaled
    }
    __syncthreads();
    // One-time: all CTAs' sentinels visible before any remote store.
    asm volatile("barrier.cluster.arrive.aligned;" ::: "memory");
    asm volatile("barrier.cluster.wait.aligned;"   ::: "memory");

    // Precomputed addresses for BOTH buffers (no per-iter select).
    uint32_t dstb = 0;
    if (!owner)
        dstb = mapa_rank(smem_u32(&inbox[0][0]), (uint32_t)own)
             + (uint32_t)(((o & 31) << 3) + (int)rank) * 4u;
    const uint32_t BUFB = INBOX_WORDS * 4u;
    const uint32_t dst0 = dstb,                 dst1 = dstb + BUFB;
    const uint32_t rbb  = smem_u32(&inbox[0][(o & 31) << 3]);
    const uint32_t rb0  = rbb,                  rb1  = rbb + BUFB;
    const uint32_t dep0 = rb0 + (uint32_t)rank * 4u;
    const uint32_t dep1 = rb1 + (uint32_t)rank * 4u;

    // One step: consume hbuf[CUR], ship/collect via (rb,dst,dep), publish
    // hbuf[CUR^1]. 'pre' guards the xproj prefetch for step tnext.
    auto body = [&](int CUR, uint32_t rb, uint32_t dstA, uint32_t dep,
                    bool pre, int tnext) {
        float bxp_next = 0.f;
        if (owner && pre)
            bxp_next = bias + __ldg(&g_xproj[tnext * HID + o]);

        // ---- 32-MAC partial: 4 chains (depth 4) + packed add2 tree ----
        const ulonglong2* h2 =
            reinterpret_cast<const ulonglong2*>(&hbuf[CUR][0]);
        ulonglong2 hv0 = h2[0], hv1 = h2[1], hv2 = h2[2], hv3 = h2[3];
        ulonglong2 hv4 = h2[4], hv5 = h2[5], hv6 = h2[6], hv7 = h2[7];
        unsigned long long a0 = 0ull, a1 = 0ull, a2 = 0ull, a3 = 0ull;
        fma2(a0, w[0],  hv0.x); fma2(a1, w[1],  hv0.y);
        fma2(a2, w[2],  hv1.x); fma2(a3, w[3],  hv1.y);
        fma2(a0, w[4],  hv2.x); fma2(a1, w[5],  hv2.y);
        fma2(a2, w[6],  hv3.x); fma2(a3, w[7],  hv3.y);
        fma2(a0, w[8],  hv4.x); fma2(a1, w[9],  hv4.y);
        fma2(a2, w[10], hv5.x); fma2(a3, w[11], hv5.y);
        fma2(a0, w[12], hv6.x); fma2(a1, w[13], hv6.y);
        fma2(a2, w[14], hv7.x); fma2(a3, w[15], hv7.y);
        unsigned long long b0, b1, sp;
        add2(b0, a0, a1); add2(b1, a2, a3); add2(sp, b0, b1);
        float x0, y0;
        unpack2(sp, x0, y0);
        float s = x0 + y0;

        if (!owner) {
            st_remote_f32(dstA, s);                 // ship to owner CTA
        } else {
            stsv1(dep, __float_as_uint(s + bxp));   // deposit own partial
            unsigned v0, v1, v2, v3, v4, v5, v6, v7;
            for (;;) {
                ldsv4(rb,      v0, v1, v2, v3);
                ldsv4(rb + 16, v4, v5, v6, v7);
                if (v0 != SENTB && v1 != SENTB && v2 != SENTB && v3 != SENTB &&
                    v4 != SENTB && v5 != SENTB && v6 != SENTB && v7 != SENTB)
                    break;
            }
            stsv4(rb,      SENTB, SENTB, SENTB, SENTB);   // re-arm for t+2
            stsv4(rb + 16, SENTB, SENTB, SENTB, SENTB);

            float z = ((__uint_as_float(v0) + __uint_as_float(v1)) +
                       (__uint_as_float(v2) + __uint_as_float(v3))) +
                      ((__uint_as_float(v4) + __uint_as_float(v5)) +
                       (__uint_as_float(v6) + __uint_as_float(v7)));
            hn = sigmoid_scaled(z);                 // z is -z_true*log2e
            hbuf[CUR ^ 1][o & 31] = hn;
            bxp = bxp_next;
        }
        __syncthreads();   // publish hbuf[nxt]; drain re-arm; reads done
    };

    #pragma unroll 1
    for (int t = 0; t < SEQ; t += 2) {
        body(0, rb0, dst0, dep0, true,          t + 1);
        body(1, rb1, dst1, dep1, t + 2 < SEQ,   t + 2);
    }

    if (owner) out[o] = hn;
}

// ---------------------------------------------------------------------------
// kernel_launch
//   d_in: [0] tokens i32[4096], [1] embedding f32[128000*256],
//         [2] wx_w f32[256*256], [3] wx_b f32[256],
//         [4] wh_w f32[256*256], [5] wh_b f32[256]
// ---------------------------------------------------------------------------
extern "C" void kernel_launch(void* const* d_in, const int* in_sizes, int n_in,
                              void* d_out, int out_size)
{
    const int*   tokens    = (const int*)d_in[0];
    const float* embedding = (const float*)d_in[1];
    const float* wx_w      = (const float*)d_in[2];
    const float* wx_b      = (const float*)d_in[3];
    const float* wh_w      = (const float*)d_in[4];
    const float* wh_b      = (const float*)d_in[5];
    float*       out       = (float*)d_out;

    xproj_kernel<<<SEQ / TOK_PER_BLK, 256>>>(tokens, embedding, wx_w, wx_b);
    rnn_kernel<<<NCTA, THREADS2>>>(wh_w, wh_b, out);
}